// round 1
// baseline (speedup 1.0000x reference)
#include <cuda_runtime.h>
#include <cstdint>

// ============================================================================
// SphericalHarmonicsShellsConv — fused gather + per-voxel GEMM + CG contraction
//
// Shapes (fixed): B=4, N=4096, V=2048, P=32, C=16, BV=8192
// signal channels: x0:16 | x1:48 | x2:80 | x3:112  => 256
// kernels y-dim: 4 | 9 | 10 | 7 => 30
// outputs (concat flat): J=0:(8192,1,160) J=1:(8192,3,336) J=2:(8192,5,384)
//                        J=3:(8192,7,320)
// ============================================================================

#define NBV     8192
#define NGROUPS 333
#define MAXE    49

// ---------------- device tables (built per-launch by init kernels) ----------
__device__ float g_cg[27 * 343];            // dense real CG tensors
__device__ int2  g_ent[NGROUPS * MAXE];     // (ysm addr, float bits of coeff)
__device__ int2  g_desc[NGROUPS];           // (local out offset, J | nnz<<8)

// ---------------- static structure tables -----------------------------------
// 27 CG triples (j,l,J)
__constant__ unsigned char TRI_J [27] = {1,1,1, 2,2,2, 3,3, 1,1,1, 2,2,2,2, 3,3,3, 1,1, 2,2,2, 3,3,3,3};
__constant__ unsigned char TRI_L [27] = {1,1,1, 1,1,1, 1,1, 2,2,2, 2,2,2,2, 2,2,2, 3,3, 3,3,3, 3,3,3,3};
__constant__ unsigned char TRI_JO[27] = {0,1,2, 1,2,3, 2,3, 1,2,3, 0,1,2,3, 1,2,3, 2,3, 1,2,3, 0,1,2,3};

// 34 output segments in concat order. type: 0=copy(l=0,j=J), 1=copy(j=0,l=J), 2=CG
__constant__ unsigned char SEG_TYPE[34] = {0,2,2,2,  0,1,2,2,2,2,2,2,2,  0,1,2,2,2,2,2,2,2,2,2,  0,1,2,2,2,2,2,2,2,2};
__constant__ unsigned char SEG_J  [34] = {0,1,2,3,  1,0,1,2,1,2,3,2,3,  2,0,1,2,3,1,2,3,1,2,3,  3,0,2,3,1,2,3,1,2,3};
__constant__ unsigned char SEG_L  [34] = {0,1,2,3,  0,1,1,1,2,2,2,3,3,  0,2,1,1,1,2,2,2,3,3,3,  0,3,1,1,2,2,2,3,3,3};
__constant__ unsigned char SEG_CG [34] = {255,0,11,23, 255,255,1,3,8,12,15,20,24, 255,255,2,4,6,9,13,16,18,21,25, 255,255,5,7,10,14,17,19,22,26};
__constant__ unsigned char SEG_W  [34] = {4,3,2,1,  3,4,3,2,3,2,1,2,1,  2,4,3,2,1,3,2,1,3,2,1,  1,4,2,1,3,2,1,3,2,1};
__constant__ int SEGSTART[4] = {0, 4, 13, 24};
__constant__ int GROW[4]     = {10, 21, 24, 20};       // groups per output row
__constant__ int CHJ[4]      = {160, 336, 384, 320};   // channels per output row
__constant__ int YOFF[4]     = {0, 4, 13, 23};
__constant__ int COFF[4]     = {0, 16, 64, 144};
__constant__ long long OUT_BASE[4] = {0LL, 1310720LL, 9568256LL, 25296896LL};
__constant__ int PERBV[4]    = {160, 1008, 1920, 2240};

// ---------------- complex helpers (double) ----------------------------------
struct cd { double x, y; };
__device__ __forceinline__ cd cmul(cd a, cd b) {
    return cd{a.x * b.x - a.y * b.y, a.x * b.y + a.y * b.x};
}

__device__ double dfact(int n) {
    double r = 1.0;
    for (int i = 2; i <= n; i++) r *= (double)i;
    return r;
}

__device__ double su2cg(int j1, int m1, int j2, int m2, int j3, int m3) {
    if (m3 != m1 + m2) return 0.0;
    int vmin = max(max(-j1 + j2 + m3, -j1 + m1), 0);
    int vmax = min(min(j2 + j3 + m1, j3 - j1 + j2), j3 + m3);
    if (vmax < vmin) return 0.0;
    double C = sqrt((2.0 * j3 + 1.0) * dfact(j3 + j1 - j2) * dfact(j3 - j1 + j2) *
                    dfact(j1 + j2 - j3) * dfact(j3 + m3) * dfact(j3 - m3) /
                    (dfact(j1 + j2 + j3 + 1) * dfact(j1 - m1) * dfact(j1 + m1) *
                     dfact(j2 - m2) * dfact(j2 + m2)));
    double S = 0.0;
    for (int v = vmin; v <= vmax; v++) {
        double t = dfact(j2 + j3 + m1 - v) * dfact(j1 - m1 + v) /
                   (dfact(v) * dfact(j3 - j1 + j2 - v) * dfact(j3 + m3 - v) *
                    dfact(v + j1 - j2 - m3));
        if ((v + j2 + m2) & 1) t = -t;
        S += t;
    }
    return C * S;
}

// q_real_to_complex entry: row r (complex m index = r-l), col c (real index)
__device__ cd qent(int l, int r, int c) {
    const double s2 = 0.7071067811865476;
    int m = r - l;
    double re = 0.0, im = 0.0;
    if (m < 0) {
        if (c == l - m)      re = s2;
        else if (c == l + m) im = -s2;
    } else if (m == 0) {
        if (c == l) re = 1.0;
    } else {
        double sg = (m & 1) ? -1.0 : 1.0;
        if (c == l + m)      re = sg * s2;
        else if (c == l - m) im = sg * s2;
    }
    double ore, oim;
    switch (l & 3) {               // multiply by (-i)^l
        case 0:  ore = re;  oim = im;  break;
        case 1:  ore = im;  oim = -re; break;
        case 2:  ore = -re; oim = -im; break;
        default: ore = -im; oim = re;  break;
    }
    return cd{ore, oim};
}

// ---------------- init kernel 1: dense real CG tensors ----------------------
__global__ void shc_init_cg() {
    const int t27 = blockIdx.x;                 // 0..26
    const int j = TRI_J[t27], l = TRI_L[t27], J = TRI_JO[t27];
    const int nj = 2 * j + 1, nl = 2 * l + 1, nJ = 2 * J + 1;
    __shared__ double su2[7][7];

    for (int idx = threadIdx.x; idx < nj * nl; idx += blockDim.x) {
        int i = idx / nl, k = idx % nl;
        int m1 = i - j, m2 = k - l, m3 = m1 + m2;
        su2[i][k] = (abs(m3) <= J) ? su2cg(j, m1, l, m2, J, m3) : 0.0;
    }
    __syncthreads();

    for (int idx = threadIdx.x; idx < nj * nl * nJ; idx += blockDim.x) {
        int a  = idx / (nl * nJ);
        int r1 = idx % (nl * nJ);
        int b  = r1 / nJ;
        int cc = r1 % nJ;
        double ar = 0.0;
        for (int i = 0; i < nj; i++) {
            cd q1 = qent(j, i, a);
            if (q1.x == 0.0 && q1.y == 0.0) continue;
            for (int k = 0; k < nl; k++) {
                double s = su2[i][k];
                if (s == 0.0) continue;
                cd q2 = qent(l, k, b);
                if (q2.x == 0.0 && q2.y == 0.0) continue;
                int n = J + (i - j) + (k - l);
                cd q3 = qent(J, n, cc);
                q3.y = -q3.y;                    // conj
                cd tt = cmul(cmul(q1, q2), q3);
                ar += tt.x * s;
            }
        }
        g_cg[t27 * 343 + idx] = (float)ar;
    }
}

// ---------------- init kernel 2: compact sparse group table -----------------
__global__ void shc_build_table() {
    int g = threadIdx.x;
    if (g >= NGROUPS) return;
    int J, base;
    if (g < 10)       { J = 0; base = 0;   }
    else if (g < 73)  { J = 1; base = 10;  }
    else if (g < 193) { J = 2; base = 73;  }
    else              { J = 3; base = 193; }
    int idx = g - base;
    int row = idx / GROW[J];
    int gr  = idx % GROW[J];
    int s = SEGSTART[J], accw = 0;
    while (gr >= accw + SEG_W[s]) { accw += SEG_W[s]; s++; }
    int u = gr - accw;
    int local = row * CHJ[J] + gr * 16;
    int eb = g * MAXE;
    int nnz;
    int type = SEG_TYPE[s];
    if (type == 0) {            // l=0 copy, j=J: y[yoff[J]+row*(4-J)+u, ch]
        g_ent[eb] = make_int2((YOFF[J] + row * (4 - J) + u) * 256, __float_as_int(1.0f));
        nnz = 1;
    } else if (type == 1) {     // j=0 copy, l=J: y[u, coff[J]+row*16+ch]
        g_ent[eb] = make_int2(u * 256 + COFF[J] + row * 16, __float_as_int(1.0f));
        nnz = 1;
    } else {
        int jj = SEG_J[s], ll = SEG_L[s];
        const float* C = g_cg + (int)SEG_CG[s] * 343;
        int nj = 2 * jj + 1, nl2 = 2 * ll + 1, nJ = 2 * J + 1;
        nnz = 0;
        for (int n = 0; n < nj; n++)
            for (int m = 0; m < nl2; m++) {
                float v = C[(n * nl2 + m) * nJ + row];
                if (fabsf(v) > 1e-6f) {
                    g_ent[eb + nnz] = make_int2(
                        (YOFF[jj] + n * (4 - jj) + u) * 256 + COFF[ll] + m * 16,
                        __float_as_int(v));
                    nnz++;
                }
            }
    }
    g_desc[g] = make_int2(local, J | (nnz << 8));
}

// ---------------- main fused kernel -----------------------------------------
__global__ void __launch_bounds__(128)
shc_main(const float* __restrict__ x0, const float* __restrict__ x1,
         const float* __restrict__ x2, const float* __restrict__ x3,
         const int*  __restrict__ pidx, const float* __restrict__ kern,
         float* __restrict__ out)
{
    __shared__ float2 ksm[32 * 32];   // [p][y] with K value duplicated (k,k), y padded to 32
    __shared__ int    nrow[32];       // gathered flat row index b*N + n
    __shared__ float  ysm[30 * 256];  // y[yidx][c]

    const int t  = threadIdx.x;       // 128 threads, 2 channels each
    const int bv = blockIdx.x;

    // load K (32x30) duplicated into pairs
    const float* kb = kern + (long long)bv * 960;
    #pragma unroll
    for (int i = 0; i < 8; i++) {
        int idx = t + i * 128;
        if (idx < 960) {
            float v = kb[idx];
            int p = idx / 30, y = idx - p * 30;
            ksm[p * 32 + y] = make_float2(v, v);
        }
    }
    if (t < 32) {
        int2 pr = ((const int2*)pidx)[(long long)bv * 32 + t];
        nrow[t] = pr.x * 4096 + pr.y;
    }
    __syncthreads();

    // this thread's two adjacent channels c, c+1 (pairs never straddle arrays)
    const int c = t * 2;
    const float* src; int chl;
    if (c < 16)       { src = x0 + c;         chl = 16;  }
    else if (c < 64)  { src = x1 + (c - 16);  chl = 48;  }
    else if (c < 144) { src = x2 + (c - 64);  chl = 80;  }
    else              { src = x3 + (c - 144); chl = 112; }

    unsigned long long acc[30];
    #pragma unroll
    for (int y = 0; y < 30; y++) acc[y] = 0ull;

    #pragma unroll 4
    for (int p = 0; p < 32; p++) {
        unsigned long long s =
            *reinterpret_cast<const unsigned long long*>(src + (long long)nrow[p] * chl);
        const ulonglong2* kp = reinterpret_cast<const ulonglong2*>(&ksm[p * 32]);
        #pragma unroll
        for (int h = 0; h < 15; h++) {
            ulonglong2 k2 = kp[h];
            asm("fma.rn.f32x2 %0, %1, %2, %0;" : "+l"(acc[2 * h])     : "l"(s), "l"(k2.x));
            asm("fma.rn.f32x2 %0, %1, %2, %0;" : "+l"(acc[2 * h + 1]) : "l"(s), "l"(k2.y));
        }
    }
    #pragma unroll
    for (int y = 0; y < 30; y++)
        *reinterpret_cast<unsigned long long*>(&ysm[y * 256 + c]) = acc[y];
    __syncthreads();

    // stage 2: sparse CG contraction + copies, 16 lanes per channel group
    const int ch = t & 15;
    for (int g = (t >> 4); g < NGROUPS; g += 8) {
        int2 d = g_desc[g];
        int J   = d.y & 0xFF;
        int nnz = d.y >> 8;
        const int2* ep = g_ent + g * MAXE;
        float v = 0.0f;
        for (int k = 0; k < nnz; k++) {
            int2 e = ep[k];
            v = fmaf(__int_as_float(e.y), ysm[e.x + ch], v);
        }
        out[OUT_BASE[J] + (long long)bv * PERBV[J] + d.x + ch] = v;
    }
}

// ---------------- launch -----------------------------------------------------
extern "C" void kernel_launch(void* const* d_in, const int* in_sizes, int n_in,
                              void* d_out, int out_size)
{
    const float* x0   = (const float*)d_in[0];
    const float* x1   = (const float*)d_in[1];
    const float* x2   = (const float*)d_in[2];
    const float* x3   = (const float*)d_in[3];
    const int*   pidx = (const int*)  d_in[4];
    const float* kern = (const float*)d_in[5];
    float* out = (float*)d_out;

    shc_init_cg<<<27, 128>>>();
    shc_build_table<<<1, 352>>>();
    shc_main<<<NBV, 128>>>(x0, x1, x2, x3, pidx, kern, out);
}

// round 3
// speedup vs baseline: 1.1488x; 1.1488x over previous
#include <cuda_runtime.h>
#include <cstdint>

// ============================================================================
// SphericalHarmonicsShellsConv — fused gather + per-voxel GEMM + CG contraction
// Shapes (fixed): B=4, N=4096, V=2048, P=32, C=16, BV=8192
// ============================================================================

#define NBV     8192
#define NGROUPS 333
#define MAXENT  4096

// ---------------- device tables (built per-launch by init kernels) ----------
__device__ float g_cg[27 * 343];          // dense real CG tensors
__device__ int2  g_e[MAXENT];             // compact entries: (ysm addr, coeff bits)
__device__ int2  g_desc[NGROUPS];         // (local out offset, J | nnz<<2 | off<<16)

// ---------------- static structure tables -----------------------------------
__constant__ unsigned char TRI_J [27] = {1,1,1, 2,2,2, 3,3, 1,1,1, 2,2,2,2, 3,3,3, 1,1, 2,2,2, 3,3,3,3};
__constant__ unsigned char TRI_L [27] = {1,1,1, 1,1,1, 1,1, 2,2,2, 2,2,2,2, 2,2,2, 3,3, 3,3,3, 3,3,3,3};
__constant__ unsigned char TRI_JO[27] = {0,1,2, 1,2,3, 2,3, 1,2,3, 0,1,2,3, 1,2,3, 2,3, 1,2,3, 0,1,2,3};

__constant__ unsigned char SEG_TYPE[34] = {0,2,2,2,  0,1,2,2,2,2,2,2,2,  0,1,2,2,2,2,2,2,2,2,2,  0,1,2,2,2,2,2,2,2,2};
__constant__ unsigned char SEG_J  [34] = {0,1,2,3,  1,0,1,2,1,2,3,2,3,  2,0,1,2,3,1,2,3,1,2,3,  3,0,2,3,1,2,3,1,2,3};
__constant__ unsigned char SEG_L  [34] = {0,1,2,3,  0,1,1,1,2,2,2,3,3,  0,2,1,1,1,2,2,2,3,3,3,  0,3,1,1,2,2,2,3,3,3};
__constant__ unsigned char SEG_CG [34] = {255,0,11,23, 255,255,1,3,8,12,15,20,24, 255,255,2,4,6,9,13,16,18,21,25, 255,255,5,7,10,14,17,19,22,26};
__constant__ unsigned char SEG_W  [34] = {4,3,2,1,  3,4,3,2,3,2,1,2,1,  2,4,3,2,1,3,2,1,3,2,1,  1,4,2,1,3,2,1,3,2,1};
__constant__ int SEGSTART[4] = {0, 4, 13, 24};
__constant__ int GROW[4]     = {10, 21, 24, 20};
__constant__ int CHJ[4]      = {160, 336, 384, 320};
__constant__ int YOFF[4]     = {0, 4, 13, 23};
__constant__ int COFF[4]     = {0, 16, 64, 144};
__constant__ long long OUT_BASE[4] = {0LL, 1310720LL, 9568256LL, 25296896LL};
__constant__ int PERBV[4]    = {160, 1008, 1920, 2240};

// ---------------- float complex helpers --------------------------------------
struct cf { float x, y; };
__device__ __forceinline__ cf cmulf(cf a, cf b) {
    return cf{a.x * b.x - a.y * b.y, a.x * b.y + a.y * b.x};
}

__device__ __forceinline__ float ffact(int n) {
    float r = 1.0f;
    for (int i = 2; i <= n; i++) r *= (float)i;
    return r;
}

__device__ float su2cgf(int j1, int m1, int j2, int m2, int j3, int m3) {
    if (m3 != m1 + m2) return 0.0f;
    int vmin = max(max(-j1 + j2 + m3, -j1 + m1), 0);
    int vmax = min(min(j2 + j3 + m1, j3 - j1 + j2), j3 + m3);
    if (vmax < vmin) return 0.0f;
    float C = sqrtf((2.0f * j3 + 1.0f) * ffact(j3 + j1 - j2) * ffact(j3 - j1 + j2) *
                    ffact(j1 + j2 - j3) * ffact(j3 + m3) * ffact(j3 - m3) /
                    (ffact(j1 + j2 + j3 + 1) * ffact(j1 - m1) * ffact(j1 + m1) *
                     ffact(j2 - m2) * ffact(j2 + m2)));
    float S = 0.0f;
    for (int v = vmin; v <= vmax; v++) {
        float t = ffact(j2 + j3 + m1 - v) * ffact(j1 - m1 + v) /
                  (ffact(v) * ffact(j3 - j1 + j2 - v) * ffact(j3 + m3 - v) *
                   ffact(v + j1 - j2 - m3));
        if ((v + j2 + m2) & 1) t = -t;
        S += t;
    }
    return C * S;
}

// q_real_to_complex entry: row r (complex m = r-l), col c (real index)
__device__ cf qentf(int l, int r, int c) {
    const float s2 = 0.70710678118654752f;
    int m = r - l;
    float re = 0.0f, im = 0.0f;
    if (m < 0) {
        if (c == l - m)      re = s2;
        else if (c == l + m) im = -s2;
    } else if (m == 0) {
        if (c == l) re = 1.0f;
    } else {
        float sg = (m & 1) ? -1.0f : 1.0f;
        if (c == l + m)      re = sg * s2;
        else if (c == l - m) im = sg * s2;
    }
    float ore, oim;
    switch (l & 3) {               // multiply by (-i)^l
        case 0:  ore = re;  oim = im;  break;
        case 1:  ore = im;  oim = -re; break;
        case 2:  ore = -re; oim = -im; break;
        default: ore = -im; oim = re;  break;
    }
    return cf{ore, oim};
}

// ---------------- init kernel 1: dense real CG tensors (float) ---------------
__global__ void shc_init_cg() {
    const int t27 = blockIdx.x;
    const int j = TRI_J[t27], l = TRI_L[t27], J = TRI_JO[t27];
    const int nj = 2 * j + 1, nl = 2 * l + 1, nJ = 2 * J + 1;
    __shared__ float su2[7][7];

    for (int idx = threadIdx.x; idx < nj * nl; idx += blockDim.x) {
        int i = idx / nl, k = idx % nl;
        int m1 = i - j, m2 = k - l, m3 = m1 + m2;
        su2[i][k] = (abs(m3) <= J) ? su2cgf(j, m1, l, m2, J, m3) : 0.0f;
    }
    __syncthreads();

    for (int idx = threadIdx.x; idx < nj * nl * nJ; idx += blockDim.x) {
        int a  = idx / (nl * nJ);
        int r1 = idx % (nl * nJ);
        int b  = r1 / nJ;
        int cc = r1 % nJ;
        float ar = 0.0f;
        for (int i = 0; i < nj; i++) {
            cf q1 = qentf(j, i, a);
            if (q1.x == 0.0f && q1.y == 0.0f) continue;
            for (int k = 0; k < nl; k++) {
                float s = su2[i][k];
                if (s == 0.0f) continue;
                cf q2 = qentf(l, k, b);
                if (q2.x == 0.0f && q2.y == 0.0f) continue;
                int n = J + (i - j) + (k - l);
                cf q3 = qentf(J, n, cc);
                q3.y = -q3.y;                    // conj
                cf tt = cmulf(cmulf(q1, q2), q3);
                ar += tt.x * s;
            }
        }
        g_cg[t27 * 343 + idx] = ar;
    }
}

// ---------------- init kernel 2: compact sparse group table ------------------
__global__ void shc_build_table() {
    __shared__ int nnzs[NGROUPS];
    __shared__ int offs[NGROUPS];

    const int g = threadIdx.x;
    int J = 0, local = 0;
    int   la[49];
    float lv[49];
    int nnz = 0;

    if (g < NGROUPS) {
        int base;
        if (g < 10)       { J = 0; base = 0;   }
        else if (g < 73)  { J = 1; base = 10;  }
        else if (g < 193) { J = 2; base = 73;  }
        else              { J = 3; base = 193; }
        int idx = g - base;
        int row = idx / GROW[J];
        int gr  = idx % GROW[J];
        int s = SEGSTART[J], accw = 0;
        while (gr >= accw + SEG_W[s]) { accw += SEG_W[s]; s++; }
        int u = gr - accw;
        local = row * CHJ[J] + gr * 16;

        int type = SEG_TYPE[s];
        if (type == 0) {            // l=0 copy, j=J
            la[0] = (YOFF[J] + row * (4 - J) + u) * 256;
            lv[0] = 1.0f;
            nnz = 1;
        } else if (type == 1) {     // j=0 copy, l=J
            la[0] = u * 256 + COFF[J] + row * 16;
            lv[0] = 1.0f;
            nnz = 1;
        } else {
            int jj = SEG_J[s], ll = SEG_L[s];
            const float* C = g_cg + (int)SEG_CG[s] * 343;
            int nj = 2 * jj + 1, nl2 = 2 * ll + 1, nJ = 2 * J + 1;
            for (int n = 0; n < nj; n++)
                for (int m = 0; m < nl2; m++) {
                    float v = C[(n * nl2 + m) * nJ + row];
                    if (fabsf(v) > 1e-6f) {
                        la[nnz] = (YOFF[jj] + n * (4 - jj) + u) * 256 +
                                  COFF[ll] + m * 16;
                        lv[nnz] = v;
                        nnz++;
                    }
                }
        }
        nnzs[g] = nnz;
    }
    __syncthreads();
    if (threadIdx.x == 0) {
        int acc = 0;
        for (int i = 0; i < NGROUPS; i++) { offs[i] = acc; acc += nnzs[i]; }
    }
    __syncthreads();
    if (g < NGROUPS) {
        int off = offs[g];
        for (int k = 0; k < nnz; k++)
            g_e[off + k] = make_int2(la[k], __float_as_int(lv[k]));
        g_desc[g] = make_int2(local, J | (nnz << 2) | (off << 16));
    }
}

// ---------------- main fused kernel -----------------------------------------
__global__ void __launch_bounds__(128, 4)
shc_main(const float* __restrict__ x0, const float* __restrict__ x1,
         const float* __restrict__ x2, const float* __restrict__ x3,
         const int*  __restrict__ pidx, const float* __restrict__ kern,
         float* __restrict__ out)
{
    __shared__ float2 ksm[32 * 32];   // [p][y], K value duplicated (k,k)
    __shared__ int    nrow[32];       // gathered flat row index b*N + n
    __shared__ float  ysm[30 * 256];  // y[yidx][c]

    const int t  = threadIdx.x;
    const int bv = blockIdx.x;

    // load K (32x30) duplicated into pairs
    const float* kb = kern + (long long)bv * 960;
    #pragma unroll
    for (int i = 0; i < 8; i++) {
        int idx = t + i * 128;
        if (idx < 960) {
            float v = kb[idx];
            int p = idx / 30, y = idx - p * 30;
            ksm[p * 32 + y] = make_float2(v, v);
        }
    }
    if (t < 32) {
        int2 pr = ((const int2*)pidx)[(long long)bv * 32 + t];
        nrow[t] = pr.x * 4096 + pr.y;
    }
    __syncthreads();

    // this thread's two adjacent channels c, c+1 (pairs never straddle arrays)
    const int c = t * 2;
    const float* src; int chl;
    if (c < 16)       { src = x0 + c;         chl = 16;  }
    else if (c < 64)  { src = x1 + (c - 16);  chl = 48;  }
    else if (c < 144) { src = x2 + (c - 64);  chl = 80;  }
    else              { src = x3 + (c - 144); chl = 112; }

    unsigned long long acc[30];
    #pragma unroll
    for (int y = 0; y < 30; y++) acc[y] = 0ull;

    // software-pipelined gather + packed FMA
    unsigned long long s_cur =
        *reinterpret_cast<const unsigned long long*>(src + (long long)nrow[0] * chl);
    #pragma unroll 4
    for (int p = 0; p < 32; p++) {
        unsigned long long s = s_cur;
        if (p < 31)
            s_cur = *reinterpret_cast<const unsigned long long*>(
                        src + (long long)nrow[p + 1] * chl);
        const ulonglong2* kp = reinterpret_cast<const ulonglong2*>(&ksm[p * 32]);
        #pragma unroll
        for (int h = 0; h < 15; h++) {
            ulonglong2 k2 = kp[h];
            asm("fma.rn.f32x2 %0, %1, %2, %0;" : "+l"(acc[2 * h])     : "l"(s), "l"(k2.x));
            asm("fma.rn.f32x2 %0, %1, %2, %0;" : "+l"(acc[2 * h + 1]) : "l"(s), "l"(k2.y));
        }
    }
    #pragma unroll
    for (int y = 0; y < 30; y++)
        *reinterpret_cast<unsigned long long*>(&ysm[y * 256 + c]) = acc[y];
    __syncthreads();

    // stage 2: sparse CG contraction + copies (compact table, L1-resident,
    // 4-wide independent load batches)
    const int ch = t & 15;
    for (int g = (t >> 4); g < NGROUPS; g += 8) {
        int2 d = __ldg(&g_desc[g]);
        int J   = d.y & 3;
        int nnz = (d.y >> 2) & 63;
        int off = d.y >> 16;
        float v = 0.0f;
        int k = 0;
        for (; k + 4 <= nnz; k += 4) {
            int2 e0 = __ldg(&g_e[off + k]);
            int2 e1 = __ldg(&g_e[off + k + 1]);
            int2 e2 = __ldg(&g_e[off + k + 2]);
            int2 e3 = __ldg(&g_e[off + k + 3]);
            float y0 = ysm[e0.x + ch], y1 = ysm[e1.x + ch];
            float y2 = ysm[e2.x + ch], y3 = ysm[e3.x + ch];
            float v0 = __int_as_float(e0.y) * y0;
            float v1 = __int_as_float(e1.y) * y1;
            v0 = fmaf(__int_as_float(e2.y), y2, v0);
            v1 = fmaf(__int_as_float(e3.y), y3, v1);
            v += v0 + v1;
        }
        for (; k < nnz; k++) {
            int2 e = __ldg(&g_e[off + k]);
            v = fmaf(__int_as_float(e.y), ysm[e.x + ch], v);
        }
        out[OUT_BASE[J] + (long long)bv * PERBV[J] + d.x + ch] = v;
    }
}

// ---------------- launch -----------------------------------------------------
extern "C" void kernel_launch(void* const* d_in, const int* in_sizes, int n_in,
                              void* d_out, int out_size)
{
    const float* x0   = (const float*)d_in[0];
    const float* x1   = (const float*)d_in[1];
    const float* x2   = (const float*)d_in[2];
    const float* x3   = (const float*)d_in[3];
    const int*   pidx = (const int*)  d_in[4];
    const float* kern = (const float*)d_in[5];
    float* out = (float*)d_out;

    shc_init_cg<<<27, 128>>>();
    shc_build_table<<<1, 352>>>();
    shc_main<<<NBV, 128>>>(x0, x1, x2, x3, pidx, kern, out);
}